// round 1
// baseline (speedup 1.0000x reference)
#include <cuda_runtime.h>
#include <cuda_bf16.h>

// Problem constants
// B=2, N=2048, C=1024, H=16, D=64
#define SEQ   2048
#define CDIM  1024
#define NHEAD 16
#define HDIM  64
#define BATCH 2

// Scratch (device globals — no allocation allowed)
__device__ float g_q[BATCH * NHEAD * SEQ * HDIM];    // [b,h,n,d], pre-scaled by D^-0.5
__device__ float g_k[BATCH * NHEAD * SEQ * HDIM];
__device__ float g_v[BATCH * NHEAD * SEQ * HDIM];
__device__ float g_ctx[BATCH * SEQ * CDIM];          // [b,n,h*64+d]

// ---------------------------------------------------------------------------
// Kernel 1: QKV GEMM  [4096,1024] @ [1024,3072] + bias, scatter to q/k/v
// 128x128 tile, BK=8, 8x8 per thread, 256 threads.
// ---------------------------------------------------------------------------
__global__ __launch_bounds__(256) void qkv_gemm_kernel(
    const float* __restrict__ x, const float* __restrict__ w,
    const float* __restrict__ bias)
{
    const int K = 1024, NC = 3072;
    __shared__ float As[8][132];   // transposed A tile, padded
    __shared__ float Bs[8][128];

    int tid = threadIdx.x;
    int block_row = blockIdx.y * 128;
    int block_col = blockIdx.x * 128;
    int a_row = tid >> 1;            // 0..127
    int a_col = (tid & 1) * 4;       // 0 or 4
    int b_row = tid >> 5;            // 0..7
    int b_col = (tid & 31) * 4;      // 0..124
    int tx = tid & 15, ty = tid >> 4;

    float acc[8][8];
    #pragma unroll
    for (int i = 0; i < 8; i++)
        #pragma unroll
        for (int j = 0; j < 8; j++) acc[i][j] = 0.f;

    const float* Aptr = x + (long)(block_row + a_row) * K + a_col;
    const float* Bptr = w + (long)b_row * NC + block_col + b_col;

    for (int k0 = 0; k0 < K; k0 += 8) {
        float4 av = *(const float4*)(Aptr + k0);
        As[a_col + 0][a_row] = av.x;
        As[a_col + 1][a_row] = av.y;
        As[a_col + 2][a_row] = av.z;
        As[a_col + 3][a_row] = av.w;
        float4 bv = *(const float4*)(Bptr + (long)k0 * NC);
        *(float4*)&Bs[b_row][b_col] = bv;
        __syncthreads();
        #pragma unroll
        for (int k = 0; k < 8; k++) {
            float ra[8], rb[8];
            #pragma unroll
            for (int i = 0; i < 8; i++) ra[i] = As[k][ty * 8 + i];
            #pragma unroll
            for (int j = 0; j < 8; j++) rb[j] = Bs[k][tx * 8 + j];
            #pragma unroll
            for (int i = 0; i < 8; i++)
                #pragma unroll
                for (int j = 0; j < 8; j++)
                    acc[i][j] += ra[i] * rb[j];
        }
        __syncthreads();
    }

    // Epilogue: bias + scatter to [b,h,n,d]; scale Q by D^-0.5 = 0.125
    #pragma unroll
    for (int i = 0; i < 8; i++) {
        int gr = block_row + ty * 8 + i;   // b*2048+n
        int b  = gr >> 11;
        int n  = gr & 2047;
        #pragma unroll
        for (int j = 0; j < 8; j++) {
            int gc = block_col + tx * 8 + j;     // 0..3071
            float val = acc[i][j] + bias[gc];
            int which = gc >> 10;                // 0=q,1=k,2=v
            int cc = gc & 1023;
            int h = cc >> 6, d = cc & 63;
            int idx = (((b * NHEAD + h) * SEQ) + n) * HDIM + d;
            if (which == 0)      g_q[idx] = val * 0.125f;
            else if (which == 1) g_k[idx] = val;
            else                 g_v[idx] = val;
        }
    }
}

// ---------------------------------------------------------------------------
// Kernel 2: flash-style attention, fp32 SIMT.
// CTA = 64 query rows of one (b,h); loop over 64-row KV tiles, online softmax.
// blockDim 256 (16x16 thread tile, 4x4 per thread).
// Writes O directly into [b,n,h*64+d] context layout.
// ---------------------------------------------------------------------------
__global__ __launch_bounds__(256) void attn_kernel()
{
    extern __shared__ float sm[];
    float* Qs   = sm;                    // [64][64]
    float* Kt   = Qs + 64 * 64;          // transposed K tile: Kt[d*65 + n]
    float* Vs   = Kt + 64 * 65;          // [64][64] (n-major, d contiguous)
    float* Ss   = Vs + 64 * 64;          // [64][67]
    float* sm_m = Ss + 64 * 67;
    float* sm_l = sm_m + 64;
    float* sm_c = sm_l + 64;

    int tid = threadIdx.x;
    int tx = tid & 15, ty = tid >> 4;
    int bh = blockIdx.y;                 // b*16+h
    int q0 = blockIdx.x * 64;

    const float* Qg = g_q + (long)bh * (SEQ * HDIM) + (long)q0 * HDIM;
    const float* Kg = g_k + (long)bh * (SEQ * HDIM);
    const float* Vg = g_v + (long)bh * (SEQ * HDIM);

    for (int i = tid; i < 1024; i += 256)
        ((float4*)Qs)[i] = ((const float4*)Qg)[i];
    if (tid < 64) { sm_m[tid] = -3.0e38f; sm_l[tid] = 0.f; }

    float o[4][4];
    #pragma unroll
    for (int r = 0; r < 4; r++)
        #pragma unroll
        for (int c = 0; c < 4; c++) o[r][c] = 0.f;
    __syncthreads();

    for (int kv0 = 0; kv0 < SEQ; kv0 += 64) {
        // Load K (transposed into Kt) and V
        for (int i = tid; i < 1024; i += 256) {
            float4 kv = ((const float4*)(Kg + (long)kv0 * HDIM))[i];
            int n = i >> 4, d0 = (i & 15) << 2;
            Kt[(d0 + 0) * 65 + n] = kv.x;
            Kt[(d0 + 1) * 65 + n] = kv.y;
            Kt[(d0 + 2) * 65 + n] = kv.z;
            Kt[(d0 + 3) * 65 + n] = kv.w;
            ((float4*)Vs)[i] = ((const float4*)(Vg + (long)kv0 * HDIM))[i];
        }
        __syncthreads();

        // S = Q @ K^T for this thread's 4x4 block
        float s[4][4];
        #pragma unroll
        for (int r = 0; r < 4; r++)
            #pragma unroll
            for (int c = 0; c < 4; c++) s[r][c] = 0.f;
        #pragma unroll 8
        for (int kk = 0; kk < 64; kk++) {
            float qa[4], kb[4];
            #pragma unroll
            for (int r = 0; r < 4; r++) qa[r] = Qs[(ty * 4 + r) * 64 + kk];
            #pragma unroll
            for (int c = 0; c < 4; c++) kb[c] = Kt[kk * 65 + tx * 4 + c];
            #pragma unroll
            for (int r = 0; r < 4; r++)
                #pragma unroll
                for (int c = 0; c < 4; c++)
                    s[r][c] += qa[r] * kb[c];
        }
        #pragma unroll
        for (int r = 0; r < 4; r++)
            #pragma unroll
            for (int c = 0; c < 4; c++)
                Ss[(ty * 4 + r) * 67 + tx * 4 + c] = s[r][c];
        __syncthreads();

        // Online softmax: one thread per row
        if (tid < 64) {
            float mold = sm_m[tid];
            float mx = mold;
            float* row = Ss + tid * 67;
            #pragma unroll 8
            for (int j = 0; j < 64; j++) mx = fmaxf(mx, row[j]);
            float corr = __expf(mold - mx);
            float sum = 0.f;
            #pragma unroll 8
            for (int j = 0; j < 64; j++) {
                float p = __expf(row[j] - mx);
                row[j] = p;
                sum += p;
            }
            sm_l[tid] = sm_l[tid] * corr + sum;
            sm_m[tid] = mx;
            sm_c[tid] = corr;
        }
        __syncthreads();

        // Rescale O and accumulate P @ V
        #pragma unroll
        for (int r = 0; r < 4; r++) {
            float corr = sm_c[ty * 4 + r];
            #pragma unroll
            for (int c = 0; c < 4; c++) o[r][c] *= corr;
        }
        #pragma unroll 8
        for (int j = 0; j < 64; j++) {
            float pv[4], vv[4];
            #pragma unroll
            for (int r = 0; r < 4; r++) pv[r] = Ss[(ty * 4 + r) * 67 + j];
            #pragma unroll
            for (int c = 0; c < 4; c++) vv[c] = Vs[j * 64 + tx * 4 + c];
            #pragma unroll
            for (int r = 0; r < 4; r++)
                #pragma unroll
                for (int c = 0; c < 4; c++)
                    o[r][c] += pv[r] * vv[c];
        }
        __syncthreads();   // protects Kt/Vs/Ss for next tile, and sm_l finality
    }

    // Final normalize + write to [b, n, h*64+d]
    int b = bh >> 4, h = bh & 15;
    #pragma unroll
    for (int r = 0; r < 4; r++) {
        int n = q0 + ty * 4 + r;
        float inv = 1.0f / sm_l[ty * 4 + r];
        #pragma unroll
        for (int c = 0; c < 4; c++)
            g_ctx[((long)(b * SEQ + n)) * CDIM + h * HDIM + tx * 4 + c] = o[r][c] * inv;
    }
}

// ---------------------------------------------------------------------------
// Kernel 3: proj GEMM  g_ctx[4096,1024] @ w_proj[1024,1024] + b_proj -> out
// ---------------------------------------------------------------------------
__global__ __launch_bounds__(256) void proj_gemm_kernel(
    const float* __restrict__ w, const float* __restrict__ bias,
    float* __restrict__ out)
{
    const int K = 1024, NC = 1024;
    __shared__ float As[8][132];
    __shared__ float Bs[8][128];

    int tid = threadIdx.x;
    int block_row = blockIdx.y * 128;
    int block_col = blockIdx.x * 128;
    int a_row = tid >> 1;
    int a_col = (tid & 1) * 4;
    int b_row = tid >> 5;
    int b_col = (tid & 31) * 4;
    int tx = tid & 15, ty = tid >> 4;

    float acc[8][8];
    #pragma unroll
    for (int i = 0; i < 8; i++)
        #pragma unroll
        for (int j = 0; j < 8; j++) acc[i][j] = 0.f;

    const float* Aptr = g_ctx + (long)(block_row + a_row) * K + a_col;
    const float* Bptr = w + (long)b_row * NC + block_col + b_col;

    for (int k0 = 0; k0 < K; k0 += 8) {
        float4 av = *(const float4*)(Aptr + k0);
        As[a_col + 0][a_row] = av.x;
        As[a_col + 1][a_row] = av.y;
        As[a_col + 2][a_row] = av.z;
        As[a_col + 3][a_row] = av.w;
        float4 bv = *(const float4*)(Bptr + (long)k0 * NC);
        *(float4*)&Bs[b_row][b_col] = bv;
        __syncthreads();
        #pragma unroll
        for (int k = 0; k < 8; k++) {
            float ra[8], rb[8];
            #pragma unroll
            for (int i = 0; i < 8; i++) ra[i] = As[k][ty * 8 + i];
            #pragma unroll
            for (int j = 0; j < 8; j++) rb[j] = Bs[k][tx * 8 + j];
            #pragma unroll
            for (int i = 0; i < 8; i++)
                #pragma unroll
                for (int j = 0; j < 8; j++)
                    acc[i][j] += ra[i] * rb[j];
        }
        __syncthreads();
    }

    #pragma unroll
    for (int i = 0; i < 8; i++) {
        int gr = block_row + ty * 8 + i;
        #pragma unroll
        for (int j = 0; j < 8; j++) {
            int gc = block_col + tx * 8 + j;
            out[(long)gr * NC + gc] = acc[i][j] + bias[gc];
        }
    }
}

// ---------------------------------------------------------------------------
extern "C" void kernel_launch(void* const* d_in, const int* in_sizes, int n_in,
                              void* d_out, int out_size)
{
    const float* x      = (const float*)d_in[0];
    const float* w_qkv  = (const float*)d_in[1];
    const float* b_qkv  = (const float*)d_in[2];
    const float* w_proj = (const float*)d_in[3];
    const float* b_proj = (const float*)d_in[4];
    float* out = (float*)d_out;

    // Attention kernel needs ~66 KB dynamic smem (> 48 KB default)
    const int attn_smem = (64 * 64 + 64 * 65 + 64 * 64 + 64 * 67 + 3 * 64) * (int)sizeof(float);
    cudaFuncSetAttribute(attn_kernel, cudaFuncAttributeMaxDynamicSharedMemorySize, attn_smem);

    // 1) QKV projection: [4096,1024] @ [1024,3072]
    qkv_gemm_kernel<<<dim3(3072 / 128, 4096 / 128), 256>>>(x, w_qkv, b_qkv);

    // 2) Attention: grid = (query tiles, b*h)
    attn_kernel<<<dim3(SEQ / 64, BATCH * NHEAD), 256, attn_smem>>>();

    // 3) Output projection: [4096,1024] @ [1024,1024]
    proj_gemm_kernel<<<dim3(1024 / 128, 4096 / 128), 256>>>(w_proj, b_proj, out);
}

// round 2
// speedup vs baseline: 3.4286x; 3.4286x over previous
#include <cuda_runtime.h>
#include <cuda_bf16.h>
#include <cstdint>

#define SEQ   2048
#define CDIM  1024
#define NHEAD 16
#define HDIM  64
#define BATCH 2

// ---------------------------------------------------------------------------
// Device-global scratch (no allocations allowed)
// ---------------------------------------------------------------------------
__device__ float g_rx [BATCH * SEQ * CDIM];      // tf32-rounded x
__device__ float g_rwq[CDIM * 3 * CDIM];         // tf32-rounded w_qkv
__device__ float g_rwp[CDIM * CDIM];             // tf32-rounded w_proj
__device__ float g_q  [BATCH * NHEAD * SEQ * HDIM];  // [b,h,n,d], scaled + tf32
__device__ float g_k  [BATCH * NHEAD * SEQ * HDIM];
__device__ float g_v  [BATCH * NHEAD * SEQ * HDIM];
__device__ float g_ctx[BATCH * SEQ * CDIM];      // [b,n,h*64+d], tf32-rounded

// ---------------------------------------------------------------------------
// PTX helpers
// ---------------------------------------------------------------------------
__device__ __forceinline__ uint32_t f2tf32(float x) {
    uint32_t r; asm("cvt.rna.tf32.f32 %0, %1;" : "=r"(r) : "f"(x)); return r;
}
__device__ __forceinline__ void mma_tf32(float c[4], const uint32_t a[4], const uint32_t b[2]) {
    asm volatile("mma.sync.aligned.m16n8k8.row.col.f32.tf32.tf32.f32 "
        "{%0,%1,%2,%3}, {%4,%5,%6,%7}, {%8,%9}, {%0,%1,%2,%3};"
        : "+f"(c[0]), "+f"(c[1]), "+f"(c[2]), "+f"(c[3])
        : "r"(a[0]), "r"(a[1]), "r"(a[2]), "r"(a[3]), "r"(b[0]), "r"(b[1]));
}
__device__ __forceinline__ void ldsm4(uint32_t a[4], uint32_t saddr) {
    asm volatile("ldmatrix.sync.aligned.m8n8.x4.shared.b16 {%0,%1,%2,%3}, [%4];"
        : "=r"(a[0]), "=r"(a[1]), "=r"(a[2]), "=r"(a[3]) : "r"(saddr));
}
__device__ __forceinline__ uint32_t s2u(const void* p) {
    return (uint32_t)__cvta_generic_to_shared(p);
}
__device__ __forceinline__ void cpasync16(uint32_t dst, const void* src) {
    asm volatile("cp.async.cg.shared.global [%0], [%1], 16;" :: "r"(dst), "l"(src));
}
#define CP_COMMIT asm volatile("cp.async.commit_group;")
#define CP_WAIT1  asm volatile("cp.async.wait_group 1;")

// ---------------------------------------------------------------------------
// Pre-round inputs to tf32 (round-to-nearest; avoids HW truncation bias)
// which: 0 -> g_rx, 1 -> g_rwq, 2 -> g_rwp
// ---------------------------------------------------------------------------
__global__ void round_tf32_kernel(const float* __restrict__ in, int which, int n4)
{
    float* dstf = (which == 0) ? g_rx : (which == 1) ? g_rwq : g_rwp;
    for (int i = blockIdx.x * blockDim.x + threadIdx.x; i < n4;
         i += gridDim.x * blockDim.x) {
        float4 v = ((const float4*)in)[i];
        uint4 r;
        r.x = f2tf32(v.x); r.y = f2tf32(v.y); r.z = f2tf32(v.z); r.w = f2tf32(v.w);
        ((uint4*)dstf)[i] = r;
    }
}

// ---------------------------------------------------------------------------
// TF32 tensor-core GEMM: C[4096, NC] = A[4096,1024] @ B[1024, NC] + bias
// 128x128 block tile, BK=32, 8 warps (4x2), warp tile 32x64.
// MODE 0: A=g_rx,  B=g_rwq (NC=3072): scatter to g_q/g_k/g_v (Q*0.125, tf32)
// MODE 1: A=g_ctx, B=g_rwp (NC=1024): write fp32 out + bias
// As rows stride 36 (conflict-free ldmatrix); Bs rows stride 136 (8 mod 32).
// ---------------------------------------------------------------------------
template<int NC, int MODE>
__global__ __launch_bounds__(256, 2) void mma_gemm_kernel(
    const float* __restrict__ bias, float* __restrict__ out)
{
    extern __shared__ float smem[];
    float* As = smem;                 // 2 buffers of 128*36
    float* Bs = smem + 2 * 128 * 36;  // 2 buffers of 32*136

    const float* A  = (MODE == 0) ? g_rx  : g_ctx;
    const float* Bw = (MODE == 0) ? g_rwq : g_rwp;

    const int K = 1024;
    const int tid = threadIdx.x;
    const int lane = tid & 31, warp = tid >> 5;
    const int wm = warp >> 1, wn = warp & 1;      // 4 x 2 warp grid
    const int brow = blockIdx.y * 128, bcol = blockIdx.x * 128;
    const int g = lane >> 2, tg = lane & 3;
    const int mat = lane >> 3, mr = lane & 7;

    float acc[2][8][4];
    #pragma unroll
    for (int a = 0; a < 2; a++)
        #pragma unroll
        for (int b = 0; b < 8; b++)
            #pragma unroll
            for (int c = 0; c < 4; c++) acc[a][b][c] = 0.f;

    auto stage = [&](int t, int buf) {
        float* Ad = As + buf * (128 * 36);
        float* Bd = Bs + buf * (32 * 136);
        const float* Ap = A + brow * K + t * 32;
        #pragma unroll
        for (int j = 0; j < 4; j++) {
            int f = tid + 256 * j;
            int r = f >> 3, c = (f & 7) * 4;
            cpasync16(s2u(Ad + r * 36 + c), Ap + r * K + c);
        }
        const float* Bp = Bw + (t * 32) * NC + bcol;
        #pragma unroll
        for (int j = 0; j < 4; j++) {
            int f = tid + 256 * j;
            int r = f >> 5, c = (f & 31) * 4;
            cpasync16(s2u(Bd + r * 136 + c), Bp + r * NC + c);
        }
    };

    stage(0, 0); CP_COMMIT;
    stage(1, 1); CP_COMMIT;
    CP_WAIT1; __syncthreads();

    const int nT = K / 32;
    for (int t = 0; t < nT; t++) {
        int buf = t & 1;
        const float* Ab = As + buf * (128 * 36);
        const float* Bb = Bs + buf * (32 * 136);
        #pragma unroll
        for (int kk = 0; kk < 4; kk++) {
            uint32_t af[2][4];
            #pragma unroll
            for (int mt = 0; mt < 2; mt++) {
                int row = wm * 32 + mt * 16 + (mat & 1) * 8 + mr;
                int col = kk * 8 + (mat >> 1) * 4;
                ldsm4(af[mt], s2u(Ab + row * 36 + col));
            }
            #pragma unroll
            for (int nt = 0; nt < 8; nt++) {
                uint32_t bf[2];
                bf[0] = __float_as_uint(Bb[(kk * 8 + tg) * 136 + wn * 64 + nt * 8 + g]);
                bf[1] = __float_as_uint(Bb[(kk * 8 + tg + 4) * 136 + wn * 64 + nt * 8 + g]);
                mma_tf32(acc[0][nt], af[0], bf);
                mma_tf32(acc[1][nt], af[1], bf);
            }
        }
        __syncthreads();
        if (t + 2 < nT) stage(t + 2, buf);
        CP_COMMIT;
        CP_WAIT1;
        __syncthreads();
    }

    // Epilogue
    #pragma unroll
    for (int mt = 0; mt < 2; mt++) {
        #pragma unroll
        for (int half = 0; half < 2; half++) {
            int grow = brow + wm * 32 + mt * 16 + half * 8 + g;
            #pragma unroll
            for (int nt = 0; nt < 8; nt++) {
                int gcol = bcol + wn * 64 + nt * 8 + tg * 2;
                float v0 = acc[mt][nt][half * 2 + 0] + bias[gcol];
                float v1 = acc[mt][nt][half * 2 + 1] + bias[gcol + 1];
                if (MODE == 0) {
                    int b = grow >> 11, n = grow & 2047;
                    int which = gcol >> 10, cc = gcol & 1023;
                    int h = cc >> 6, d = cc & 63;
                    int idx = ((b * NHEAD + h) * SEQ + n) * HDIM + d;
                    if (which == 0) { v0 *= 0.125f; v1 *= 0.125f; }
                    float2 val = make_float2(__uint_as_float(f2tf32(v0)),
                                             __uint_as_float(f2tf32(v1)));
                    float* dst = (which == 0) ? g_q : (which == 1) ? g_k : g_v;
                    *(float2*)&dst[idx] = val;
                } else {
                    *(float2*)&out[grow * 1024 + gcol] = make_float2(v0, v1);
                }
            }
        }
    }
}

// ---------------------------------------------------------------------------
// Flash attention with tf32 mma. CTA: 128 q-rows of one (b,h), 8 warps,
// each warp owns 16 q-rows. KV tiles of 64, 2-stage cp.async pipeline.
// Q frags live in registers for the whole loop. K consumed in natural [m][d]
// layout as col-major B (stride 68 = 4 mod 32), V likewise (stride 72 = 8
// mod 32), P via per-warp smem (stride 72). All operand reads conflict-free.
// ---------------------------------------------------------------------------
__global__ __launch_bounds__(256) void attn_mma_kernel()
{
    extern __shared__ float smem[];
    float* Qs = smem;                       // 128*68
    float* Ks = Qs + 128 * 68;              // 2 * 64*68
    float* Vs = Ks + 2 * 64 * 68;           // 2 * 64*72
    float* Ps = Vs + 2 * 64 * 72;           // 128*72

    const int tid = threadIdx.x;
    const int lane = tid & 31, warp = tid >> 5;
    const int g = lane >> 2, tg = lane & 3;
    const int mat = lane >> 3, mr = lane & 7;
    const int bh = blockIdx.y;
    const int q0 = blockIdx.x * 128;

    const float* Qg = g_q + (bh * SEQ + q0) * HDIM;
    const float* Kg = g_k + bh * SEQ * HDIM;
    const float* Vg = g_v + bh * SEQ * HDIM;

    // Stage Q (group 0, together with KV tile 0)
    #pragma unroll
    for (int j = 0; j < 8; j++) {
        int f = tid + 256 * j;
        int r = f >> 4, c = (f & 15) * 4;
        cpasync16(s2u(Qs + r * 68 + c), Qg + r * HDIM + c);
    }
    auto stageKV = [&](int t, int buf) {
        const float* Kp = Kg + t * 64 * HDIM;
        const float* Vp = Vg + t * 64 * HDIM;
        float* Kd = Ks + buf * (64 * 68);
        float* Vd = Vs + buf * (64 * 72);
        #pragma unroll
        for (int j = 0; j < 4; j++) {
            int f = tid + 256 * j;
            int r = f >> 4, c = (f & 15) * 4;
            cpasync16(s2u(Kd + r * 68 + c), Kp + r * HDIM + c);
            cpasync16(s2u(Vd + r * 72 + c), Vp + r * HDIM + c);
        }
    };

    stageKV(0, 0); CP_COMMIT;
    stageKV(1, 1); CP_COMMIT;
    CP_WAIT1; __syncthreads();

    // Q fragments (held in registers for all kv tiles)
    uint32_t qf[8][4];
    #pragma unroll
    for (int kt = 0; kt < 8; kt++) {
        int row = warp * 16 + (mat & 1) * 8 + mr;
        int col = kt * 8 + (mat >> 1) * 4;
        ldsm4(qf[kt], s2u(Qs + row * 68 + col));
    }

    float o[8][4];
    #pragma unroll
    for (int i = 0; i < 8; i++)
        #pragma unroll
        for (int j = 0; j < 4; j++) o[i][j] = 0.f;
    float m0 = -1e30f, m1 = -1e30f, l0 = 0.f, l1 = 0.f;

    const int nT = SEQ / 64;
    for (int t = 0; t < nT; t++) {
        int buf = t & 1;
        const float* Kb = Ks + buf * (64 * 68);
        const float* Vb = Vs + buf * (64 * 72);

        // S = Q @ K^T
        float sacc[8][4];
        #pragma unroll
        for (int i = 0; i < 8; i++)
            #pragma unroll
            for (int j = 0; j < 4; j++) sacc[i][j] = 0.f;

        #pragma unroll
        for (int kt = 0; kt < 8; kt++) {
            #pragma unroll
            for (int nt = 0; nt < 8; nt++) {
                uint32_t bf[2];
                bf[0] = __float_as_uint(Kb[(nt * 8 + g) * 68 + kt * 8 + tg]);
                bf[1] = __float_as_uint(Kb[(nt * 8 + g) * 68 + kt * 8 + tg + 4]);
                mma_tf32(sacc[nt], qf[kt], bf);
            }
        }

        // Online softmax (rows g and g+8 of this warp's 16-row block)
        float tm0 = -1e30f, tm1 = -1e30f;
        #pragma unroll
        for (int nt = 0; nt < 8; nt++) {
            tm0 = fmaxf(tm0, fmaxf(sacc[nt][0], sacc[nt][1]));
            tm1 = fmaxf(tm1, fmaxf(sacc[nt][2], sacc[nt][3]));
        }
        tm0 = fmaxf(tm0, __shfl_xor_sync(0xffffffffu, tm0, 1));
        tm0 = fmaxf(tm0, __shfl_xor_sync(0xffffffffu, tm0, 2));
        tm1 = fmaxf(tm1, __shfl_xor_sync(0xffffffffu, tm1, 1));
        tm1 = fmaxf(tm1, __shfl_xor_sync(0xffffffffu, tm1, 2));
        float mn0 = fmaxf(m0, tm0), mn1 = fmaxf(m1, tm1);
        float cr0 = __expf(m0 - mn0), cr1 = __expf(m1 - mn1);
        m0 = mn0; m1 = mn1;

        float sum0 = 0.f, sum1 = 0.f;
        const int r0 = warp * 16 + g;
        #pragma unroll
        for (int nt = 0; nt < 8; nt++) {
            float p0 = __expf(sacc[nt][0] - mn0);
            float p1 = __expf(sacc[nt][1] - mn0);
            float p2 = __expf(sacc[nt][2] - mn1);
            float p3 = __expf(sacc[nt][3] - mn1);
            sum0 += p0 + p1; sum1 += p2 + p3;
            *(float2*)&Ps[r0 * 72 + nt * 8 + tg * 2] =
                make_float2(__uint_as_float(f2tf32(p0)), __uint_as_float(f2tf32(p1)));
            *(float2*)&Ps[(r0 + 8) * 72 + nt * 8 + tg * 2] =
                make_float2(__uint_as_float(f2tf32(p2)), __uint_as_float(f2tf32(p3)));
        }
        sum0 += __shfl_xor_sync(0xffffffffu, sum0, 1);
        sum0 += __shfl_xor_sync(0xffffffffu, sum0, 2);
        sum1 += __shfl_xor_sync(0xffffffffu, sum1, 1);
        sum1 += __shfl_xor_sync(0xffffffffu, sum1, 2);
        l0 = l0 * cr0 + sum0;
        l1 = l1 * cr1 + sum1;

        // Rescale O
        #pragma unroll
        for (int dt = 0; dt < 8; dt++) {
            o[dt][0] *= cr0; o[dt][1] *= cr0;
            o[dt][2] *= cr1; o[dt][3] *= cr1;
        }
        __syncwarp();   // Ps visibility within the warp

        // O += P @ V
        #pragma unroll
        for (int kt = 0; kt < 8; kt++) {
            uint32_t af[4];
            af[0] = __float_as_uint(Ps[(warp * 16 + g) * 72 + kt * 8 + tg]);
            af[1] = __float_as_uint(Ps[(warp * 16 + 8 + g) * 72 + kt * 8 + tg]);
            af[2] = __float_as_uint(Ps[(warp * 16 + g) * 72 + kt * 8 + tg + 4]);
            af[3] = __float_as_uint(Ps[(warp * 16 + 8 + g) * 72 + kt * 8 + tg + 4]);
            #pragma unroll
            for (int dt = 0; dt < 8; dt++) {
                uint32_t bf[2];
                bf[0] = __float_as_uint(Vb[(kt * 8 + tg) * 72 + dt * 8 + g]);
                bf[1] = __float_as_uint(Vb[(kt * 8 + tg + 4) * 72 + dt * 8 + g]);
                mma_tf32(o[dt], af, bf);
            }
        }

        __syncthreads();
        if (t + 2 < nT) stageKV(t + 2, buf);
        CP_COMMIT;
        CP_WAIT1;
        __syncthreads();
    }

    // Epilogue: normalize, round to tf32, write [b, n, h*64+d]
    const int b = bh >> 4, h = bh & 15;
    const int n0 = q0 + warp * 16 + g;
    const float inv0 = 1.f / l0, inv1 = 1.f / l1;
    #pragma unroll
    for (int dt = 0; dt < 8; dt++) {
        int d = h * HDIM + dt * 8 + tg * 2;
        *(float2*)&g_ctx[(b * SEQ + n0) * CDIM + d] = make_float2(
            __uint_as_float(f2tf32(o[dt][0] * inv0)),
            __uint_as_float(f2tf32(o[dt][1] * inv0)));
        *(float2*)&g_ctx[(b * SEQ + n0 + 8) * CDIM + d] = make_float2(
            __uint_as_float(f2tf32(o[dt][2] * inv1)),
            __uint_as_float(f2tf32(o[dt][3] * inv1)));
    }
}

// ---------------------------------------------------------------------------
extern "C" void kernel_launch(void* const* d_in, const int* in_sizes, int n_in,
                              void* d_out, int out_size)
{
    const float* x      = (const float*)d_in[0];
    const float* w_qkv  = (const float*)d_in[1];
    const float* b_qkv  = (const float*)d_in[2];
    const float* w_proj = (const float*)d_in[3];
    const float* b_proj = (const float*)d_in[4];
    float* out = (float*)d_out;

    const int gemm_smem = (2 * 128 * 36 + 2 * 32 * 136) * (int)sizeof(float);  // 71680
    const int attn_smem = (128 * 68 + 2 * 64 * 68 + 2 * 64 * 72 + 128 * 72) * (int)sizeof(float); // 143360
    cudaFuncSetAttribute(mma_gemm_kernel<3072, 0>,
                         cudaFuncAttributeMaxDynamicSharedMemorySize, gemm_smem);
    cudaFuncSetAttribute(mma_gemm_kernel<1024, 1>,
                         cudaFuncAttributeMaxDynamicSharedMemorySize, gemm_smem);
    cudaFuncSetAttribute(attn_mma_kernel,
                         cudaFuncAttributeMaxDynamicSharedMemorySize, attn_smem);

    // 0) Round inputs to tf32 (round-to-nearest)
    round_tf32_kernel<<<2048, 256>>>(x,      0, BATCH * SEQ * CDIM / 4);
    round_tf32_kernel<<<2048, 256>>>(w_qkv,  1, CDIM * 3 * CDIM / 4);
    round_tf32_kernel<<<1024, 256>>>(w_proj, 2, CDIM * CDIM / 4);

    // 1) QKV projection (tensor cores): [4096,1024] @ [1024,3072]
    mma_gemm_kernel<3072, 0><<<dim3(3072 / 128, 4096 / 128), 256, gemm_smem>>>(b_qkv, nullptr);

    // 2) Flash attention (tensor cores)
    attn_mma_kernel<<<dim3(SEQ / 128, BATCH * NHEAD), 256, attn_smem>>>();

    // 3) Output projection (tensor cores): [4096,1024] @ [1024,1024]
    mma_gemm_kernel<1024, 1><<<dim3(1024 / 128, 4096 / 128), 256, gemm_smem>>>(b_proj, out);
}

// round 4
// speedup vs baseline: 3.8007x; 1.1085x over previous
#include <cuda_runtime.h>
#include <cuda_bf16.h>
#include <cstdint>

#define SEQ   2048
#define CDIM  1024
#define NHEAD 16
#define HDIM  64
#define BATCH 2

// ---------------------------------------------------------------------------
// Device-global scratch (no allocations allowed)
// ---------------------------------------------------------------------------
__device__ float g_q  [BATCH * NHEAD * SEQ * HDIM];  // [b,h,n,d], scaled + tf32
__device__ float g_k  [BATCH * NHEAD * SEQ * HDIM];
__device__ float g_v  [BATCH * NHEAD * SEQ * HDIM];
__device__ float g_ctx[BATCH * SEQ * CDIM];          // [b,n,h*64+d], tf32-rounded

// ---------------------------------------------------------------------------
// PTX helpers
// ---------------------------------------------------------------------------
__device__ __forceinline__ uint32_t f2tf32(float x) {
    uint32_t r; asm("cvt.rna.tf32.f32 %0, %1;" : "=r"(r) : "f"(x)); return r;
}
__device__ __forceinline__ void mma_tf32(float c[4], const uint32_t a[4], const uint32_t b[2]) {
    asm volatile("mma.sync.aligned.m16n8k8.row.col.f32.tf32.tf32.f32 "
        "{%0,%1,%2,%3}, {%4,%5,%6,%7}, {%8,%9}, {%0,%1,%2,%3};"
        : "+f"(c[0]), "+f"(c[1]), "+f"(c[2]), "+f"(c[3])
        : "r"(a[0]), "r"(a[1]), "r"(a[2]), "r"(a[3]), "r"(b[0]), "r"(b[1]));
}
__device__ __forceinline__ void ldsm4(uint32_t a[4], uint32_t saddr) {
    asm volatile("ldmatrix.sync.aligned.m8n8.x4.shared.b16 {%0,%1,%2,%3}, [%4];"
        : "=r"(a[0]), "=r"(a[1]), "=r"(a[2]), "=r"(a[3]) : "r"(saddr));
}
__device__ __forceinline__ uint32_t s2u(const void* p) {
    return (uint32_t)__cvta_generic_to_shared(p);
}
__device__ __forceinline__ void cpasync16(uint32_t dst, const void* src) {
    asm volatile("cp.async.cg.shared.global [%0], [%1], 16;" :: "r"(dst), "l"(src));
}
#define CP_COMMIT asm volatile("cp.async.commit_group;")
#define CP_WAIT1  asm volatile("cp.async.wait_group 1;")

// ---------------------------------------------------------------------------
// TF32 tensor-core GEMM: C[4096, NC] = A[4096,1024] @ B[1024, NC] + bias
// 128x128 block tile, BK=32, 8 warps (4x2), warp tile 32x64.
// MODE 0: A = x (raw fp32, rounded in-register), B = w_qkv (rounded in-reg):
//         scatter to g_q/g_k/g_v (Q*0.125, stored tf32-rounded)
// MODE 1: A = g_ctx (device global, already tf32), B = w_proj (rounded
//         in-reg): fp32 out + bias
// As rows stride 36 (conflict-free ldmatrix); Bs rows stride 136 (8 mod 32).
// ---------------------------------------------------------------------------
template<int NC, int MODE>
__global__ __launch_bounds__(256, 2) void mma_gemm_kernel(
    const float* __restrict__ Ain, const float* __restrict__ Bw,
    const float* __restrict__ bias, float* __restrict__ out)
{
    extern __shared__ float smem[];
    float* As = smem;                 // 2 buffers of 128*36
    float* Bs = smem + 2 * 128 * 36;  // 2 buffers of 32*136

    // BUGFIX (R3 crash): MODE 1 reads the device-global g_ctx, not the
    // kernel parameter (which the proj launch passes as nullptr).
    const float* A = (MODE == 1) ? (const float*)g_ctx : Ain;

    const int K = 1024;
    const int tid = threadIdx.x;
    const int lane = tid & 31, warp = tid >> 5;
    const int wm = warp >> 1, wn = warp & 1;      // 4 x 2 warp grid
    const int brow = blockIdx.y * 128, bcol = blockIdx.x * 128;
    const int g = lane >> 2, tg = lane & 3;
    const int mat = lane >> 3, mr = lane & 7;

    float acc[2][8][4];
    #pragma unroll
    for (int a = 0; a < 2; a++)
        #pragma unroll
        for (int b = 0; b < 8; b++)
            #pragma unroll
            for (int c = 0; c < 4; c++) acc[a][b][c] = 0.f;

    auto stage = [&](int t, int buf) {
        float* Ad = As + buf * (128 * 36);
        float* Bd = Bs + buf * (32 * 136);
        const float* Ap = A + brow * K + t * 32;
        #pragma unroll
        for (int j = 0; j < 4; j++) {
            int f = tid + 256 * j;
            int r = f >> 3, c = (f & 7) * 4;
            cpasync16(s2u(Ad + r * 36 + c), Ap + r * K + c);
        }
        const float* Bp = Bw + (t * 32) * NC + bcol;
        #pragma unroll
        for (int j = 0; j < 4; j++) {
            int f = tid + 256 * j;
            int r = f >> 5, c = (f & 31) * 4;
            cpasync16(s2u(Bd + r * 136 + c), Bp + r * NC + c);
        }
    };

    stage(0, 0); CP_COMMIT;
    stage(1, 1); CP_COMMIT;
    CP_WAIT1; __syncthreads();

    const int nT = K / 32;
    for (int t = 0; t < nT; t++) {
        int buf = t & 1;
        const float* Ab = As + buf * (128 * 36);
        const float* Bb = Bs + buf * (32 * 136);
        #pragma unroll
        for (int kk = 0; kk < 4; kk++) {
            uint32_t af[2][4];
            #pragma unroll
            for (int mt = 0; mt < 2; mt++) {
                int row = wm * 32 + mt * 16 + (mat & 1) * 8 + mr;
                int col = kk * 8 + (mat >> 1) * 4;
                ldsm4(af[mt], s2u(Ab + row * 36 + col));
                if (MODE == 0) {   // x is raw fp32 -> round to tf32 (RN)
                    #pragma unroll
                    for (int q = 0; q < 4; q++)
                        af[mt][q] = f2tf32(__uint_as_float(af[mt][q]));
                }
            }
            #pragma unroll
            for (int nt = 0; nt < 8; nt++) {
                uint32_t bf[2];   // weights are raw fp32 -> round to tf32
                bf[0] = f2tf32(Bb[(kk * 8 + tg) * 136 + wn * 64 + nt * 8 + g]);
                bf[1] = f2tf32(Bb[(kk * 8 + tg + 4) * 136 + wn * 64 + nt * 8 + g]);
                mma_tf32(acc[0][nt], af[0], bf);
                mma_tf32(acc[1][nt], af[1], bf);
            }
        }
        __syncthreads();
        if (t + 2 < nT) stage(t + 2, buf);
        CP_COMMIT;
        CP_WAIT1;
        __syncthreads();
    }

    // Epilogue
    #pragma unroll
    for (int mt = 0; mt < 2; mt++) {
        #pragma unroll
        for (int half = 0; half < 2; half++) {
            int grow = brow + wm * 32 + mt * 16 + half * 8 + g;
            #pragma unroll
            for (int nt = 0; nt < 8; nt++) {
                int gcol = bcol + wn * 64 + nt * 8 + tg * 2;
                float v0 = acc[mt][nt][half * 2 + 0] + bias[gcol];
                float v1 = acc[mt][nt][half * 2 + 1] + bias[gcol + 1];
                if (MODE == 0) {
                    int b = grow >> 11, n = grow & 2047;
                    int which = gcol >> 10, cc = gcol & 1023;
                    int h = cc >> 6, d = cc & 63;
                    int idx = ((b * NHEAD + h) * SEQ + n) * HDIM + d;
                    if (which == 0) { v0 *= 0.125f; v1 *= 0.125f; }
                    float2 val = make_float2(__uint_as_float(f2tf32(v0)),
                                             __uint_as_float(f2tf32(v1)));
                    float* dst = (which == 0) ? g_q : (which == 1) ? g_k : g_v;
                    *(float2*)&dst[idx] = val;
                } else {
                    *(float2*)&out[grow * 1024 + gcol] = make_float2(v0, v1);
                }
            }
        }
    }
}

// ---------------------------------------------------------------------------
// Flash attention with tf32 mma. CTA: 128 q-rows of one (b,h), 8 warps,
// each warp owns 16 q-rows. KV tiles of 64, 2-stage cp.async pipeline.
// Q frags in registers for the whole loop. P kept ENTIRELY in registers:
// C-fragment -> A-fragment layout conversion via intra-quad shuffles
// (C holds cols {2tg,2tg+1}; A needs {tg,tg+4}; rows preserved in lane quads).
// smem = Q(34KB) + 2xK(34.8KB) + 2xV(36.9KB) = 104KB -> 2 CTAs/SM.
// ---------------------------------------------------------------------------
__global__ __launch_bounds__(256, 2) void attn_mma_kernel()
{
    extern __shared__ float smem[];
    float* Qs = smem;                       // 128*68
    float* Ks = Qs + 128 * 68;              // 2 * 64*68
    float* Vs = Ks + 2 * 64 * 68;           // 2 * 64*72

    const int tid = threadIdx.x;
    const int lane = tid & 31, warp = tid >> 5;
    const int g = lane >> 2, tg = lane & 3;
    const int mat = lane >> 3, mr = lane & 7;
    const int bh = blockIdx.y;
    const int q0 = blockIdx.x * 128;

    const float* Qg = g_q + (bh * SEQ + q0) * HDIM;
    const float* Kg = g_k + bh * SEQ * HDIM;
    const float* Vg = g_v + bh * SEQ * HDIM;

    // Stage Q (with KV tile 0's group)
    #pragma unroll
    for (int j = 0; j < 8; j++) {
        int f = tid + 256 * j;
        int r = f >> 4, c = (f & 15) * 4;
        cpasync16(s2u(Qs + r * 68 + c), Qg + r * HDIM + c);
    }
    auto stageKV = [&](int t, int buf) {
        const float* Kp = Kg + t * 64 * HDIM;
        const float* Vp = Vg + t * 64 * HDIM;
        float* Kd = Ks + buf * (64 * 68);
        float* Vd = Vs + buf * (64 * 72);
        #pragma unroll
        for (int j = 0; j < 4; j++) {
            int f = tid + 256 * j;
            int r = f >> 4, c = (f & 15) * 4;
            cpasync16(s2u(Kd + r * 68 + c), Kp + r * HDIM + c);
            cpasync16(s2u(Vd + r * 72 + c), Vp + r * HDIM + c);
        }
    };

    stageKV(0, 0); CP_COMMIT;
    stageKV(1, 1); CP_COMMIT;
    CP_WAIT1; __syncthreads();

    // Q fragments (held in registers for all kv tiles)
    uint32_t qf[8][4];
    #pragma unroll
    for (int kt = 0; kt < 8; kt++) {
        int row = warp * 16 + (mat & 1) * 8 + mr;
        int col = kt * 8 + (mat >> 1) * 4;
        ldsm4(qf[kt], s2u(Qs + row * 68 + col));
    }

    float o[8][4];
    #pragma unroll
    for (int i = 0; i < 8; i++)
        #pragma unroll
        for (int j = 0; j < 4; j++) o[i][j] = 0.f;
    float m0 = -1e30f, m1 = -1e30f, l0 = 0.f, l1 = 0.f;

    const int sh0 = (lane & ~3) | (tg >> 1);   // src lane for col tg
    const int sh1 = sh0 + 2;                   // src lane for col tg+4
    const bool oddtg = (tg & 1);

    const int nT = SEQ / 64;
    for (int t = 0; t < nT; t++) {
        int buf = t & 1;
        const float* Kb = Ks + buf * (64 * 68);
        const float* Vb = Vs + buf * (64 * 72);

        // S = Q @ K^T
        float sacc[8][4];
        #pragma unroll
        for (int i = 0; i < 8; i++)
            #pragma unroll
            for (int j = 0; j < 4; j++) sacc[i][j] = 0.f;

        #pragma unroll
        for (int kt = 0; kt < 8; kt++) {
            #pragma unroll
            for (int nt = 0; nt < 8; nt++) {
                uint32_t bf[2];
                bf[0] = __float_as_uint(Kb[(nt * 8 + g) * 68 + kt * 8 + tg]);
                bf[1] = __float_as_uint(Kb[(nt * 8 + g) * 68 + kt * 8 + tg + 4]);
                mma_tf32(sacc[nt], qf[kt], bf);
            }
        }

        // Online softmax (rows g and g+8 of this warp's 16-row block)
        float tm0 = -1e30f, tm1 = -1e30f;
        #pragma unroll
        for (int nt = 0; nt < 8; nt++) {
            tm0 = fmaxf(tm0, fmaxf(sacc[nt][0], sacc[nt][1]));
            tm1 = fmaxf(tm1, fmaxf(sacc[nt][2], sacc[nt][3]));
        }
        tm0 = fmaxf(tm0, __shfl_xor_sync(0xffffffffu, tm0, 1));
        tm0 = fmaxf(tm0, __shfl_xor_sync(0xffffffffu, tm0, 2));
        tm1 = fmaxf(tm1, __shfl_xor_sync(0xffffffffu, tm1, 1));
        tm1 = fmaxf(tm1, __shfl_xor_sync(0xffffffffu, tm1, 2));
        float mn0 = fmaxf(m0, tm0), mn1 = fmaxf(m1, tm1);
        float cr0 = __expf(m0 - mn0), cr1 = __expf(m1 - mn1);
        m0 = mn0; m1 = mn1;

        // exp, accumulate row sums, convert C-layout P -> A-layout frags
        uint32_t pa[8][4];
        float sum0 = 0.f, sum1 = 0.f;
        #pragma unroll
        for (int nt = 0; nt < 8; nt++) {
            float p0 = __expf(sacc[nt][0] - mn0);
            float p1 = __expf(sacc[nt][1] - mn0);
            float p2 = __expf(sacc[nt][2] - mn1);
            float p3 = __expf(sacc[nt][3] - mn1);
            sum0 += p0 + p1; sum1 += p2 + p3;
            uint32_t r0 = f2tf32(p0), r1 = f2tf32(p1);
            uint32_t r2 = f2tf32(p2), r3 = f2tf32(p3);
            uint32_t u00 = __shfl_sync(0xffffffffu, r0, sh0);
            uint32_t u01 = __shfl_sync(0xffffffffu, r1, sh0);
            pa[nt][0] = oddtg ? u01 : u00;              // (g,    tg)
            uint32_t u10 = __shfl_sync(0xffffffffu, r2, sh0);
            uint32_t u11 = __shfl_sync(0xffffffffu, r3, sh0);
            pa[nt][1] = oddtg ? u11 : u10;              // (g+8,  tg)
            uint32_t u20 = __shfl_sync(0xffffffffu, r0, sh1);
            uint32_t u21 = __shfl_sync(0xffffffffu, r1, sh1);
            pa[nt][2] = oddtg ? u21 : u20;              // (g,    tg+4)
            uint32_t u30 = __shfl_sync(0xffffffffu, r2, sh1);
            uint32_t u31 = __shfl_sync(0xffffffffu, r3, sh1);
            pa[nt][3] = oddtg ? u31 : u30;              // (g+8,  tg+4)
        }
        sum0 += __shfl_xor_sync(0xffffffffu, sum0, 1);
        sum0 += __shfl_xor_sync(0xffffffffu, sum0, 2);
        sum1 += __shfl_xor_sync(0xffffffffu, sum1, 1);
        sum1 += __shfl_xor_sync(0xffffffffu, sum1, 2);
        l0 = l0 * cr0 + sum0;
        l1 = l1 * cr1 + sum1;

        // Rescale O
        #pragma unroll
        for (int dt = 0; dt < 8; dt++) {
            o[dt][0] *= cr0; o[dt][1] *= cr0;
            o[dt][2] *= cr1; o[dt][3] *= cr1;
        }

        // O += P @ V (P fragments entirely in registers)
        #pragma unroll
        for (int kt = 0; kt < 8; kt++) {
            #pragma unroll
            for (int dt = 0; dt < 8; dt++) {
                uint32_t bf[2];
                bf[0] = __float_as_uint(Vb[(kt * 8 + tg) * 72 + dt * 8 + g]);
                bf[1] = __float_as_uint(Vb[(kt * 8 + tg + 4) * 72 + dt * 8 + g]);
                mma_tf32(o[dt], pa[kt], bf);
            }
        }

        __syncthreads();
        if (t + 2 < nT) stageKV(t + 2, buf);
        CP_COMMIT;
        CP_WAIT1;
        __syncthreads();
    }

    // Epilogue: normalize, round to tf32, write [b, n, h*64+d]
    const int b = bh >> 4, h = bh & 15;
    const int n0 = q0 + warp * 16 + g;
    const float inv0 = 1.f / l0, inv1 = 1.f / l1;
    #pragma unroll
    for (int dt = 0; dt < 8; dt++) {
        int d = h * HDIM + dt * 8 + tg * 2;
        *(float2*)&g_ctx[(b * SEQ + n0) * CDIM + d] = make_float2(
            __uint_as_float(f2tf32(o[dt][0] * inv0)),
            __uint_as_float(f2tf32(o[dt][1] * inv0)));
        *(float2*)&g_ctx[(b * SEQ + n0 + 8) * CDIM + d] = make_float2(
            __uint_as_float(f2tf32(o[dt][2] * inv1)),
            __uint_as_float(f2tf32(o[dt][3] * inv1)));
    }
}

// ---------------------------------------------------------------------------
extern "C" void kernel_launch(void* const* d_in, const int* in_sizes, int n_in,
                              void* d_out, int out_size)
{
    const float* x      = (const float*)d_in[0];
    const float* w_qkv  = (const float*)d_in[1];
    const float* b_qkv  = (const float*)d_in[2];
    const float* w_proj = (const float*)d_in[3];
    const float* b_proj = (const float*)d_in[4];
    float* out = (float*)d_out;

    const int gemm_smem = (2 * 128 * 36 + 2 * 32 * 136) * (int)sizeof(float);  // 71680
    const int attn_smem = (128 * 68 + 2 * 64 * 68 + 2 * 64 * 72) * (int)sizeof(float); // 106496
    cudaFuncSetAttribute(mma_gemm_kernel<3072, 0>,
                         cudaFuncAttributeMaxDynamicSharedMemorySize, gemm_smem);
    cudaFuncSetAttribute(mma_gemm_kernel<1024, 1>,
                         cudaFuncAttributeMaxDynamicSharedMemorySize, gemm_smem);
    cudaFuncSetAttribute(attn_mma_kernel,
                         cudaFuncAttributeMaxDynamicSharedMemorySize, attn_smem);

    // 1) QKV projection (tensor cores): x[4096,1024] @ w_qkv[1024,3072]
    mma_gemm_kernel<3072, 0><<<dim3(3072 / 128, 4096 / 128), 256, gemm_smem>>>(
        x, w_qkv, b_qkv, nullptr);

    // 2) Flash attention (tensor cores, P in registers)
    attn_mma_kernel<<<dim3(SEQ / 128, BATCH * NHEAD), 256, attn_smem>>>();

    // 3) Output projection (tensor cores): ctx[4096,1024] @ w_proj[1024,1024]
    // A operand resolved inside the kernel (g_ctx) — R3 passed nullptr here.
    mma_gemm_kernel<1024, 1><<<dim3(1024 / 128, 4096 / 128), 256, gemm_smem>>>(
        nullptr, w_proj, b_proj, out);
}